// round 2
// baseline (speedup 1.0000x reference)
#include <cuda_runtime.h>
#include <math.h>

// Problem constants (fixed by setup_inputs)
#define EDIM 512
#define BDIM 4
#define SEQ  2048
#define NH   8
#define DH   64
#define ROWS (BDIM * SEQ)          // 8192

#define MAXNORM (1.0f - 4e-3f)     // geoopt projx eps for fp32, c=1

// ---------------- scratch (device globals: allocation-free) ----------------
__device__ float g_q[ROWS * EDIM];
__device__ float g_k[ROWS * EDIM];
__device__ float g_v[ROWS * EDIM];
__device__ float g_ao[ROWS * EDIM];
__device__ float g_qn[BDIM * NH * SEQ];
__device__ float g_kn[BDIM * NH * SEQ];

// ---------------- packed f32x2 helpers (Blackwell FFMA2) ----------------
__device__ __forceinline__ unsigned long long f2u(float x, float y) {
    unsigned long long u;
    asm("mov.b64 %0, {%1, %2};" : "=l"(u) : "f"(x), "f"(y));
    return u;
}
__device__ __forceinline__ float2 u2f2(unsigned long long u) {
    float2 f;
    asm("mov.b64 {%0, %1}, %2;" : "=f"(f.x), "=f"(f.y) : "l"(u));
    return f;
}
__device__ __forceinline__ void ffma2(unsigned long long& d,
                                      unsigned long long a, unsigned long long b) {
    asm("fma.rn.f32x2 %0, %1, %2, %0;" : "+l"(d) : "l"(a), "l"(b));
}
__device__ __forceinline__ unsigned long long mul2(unsigned long long a,
                                                   unsigned long long b) {
    unsigned long long d;
    asm("mul.rn.f32x2 %0, %1, %2;" : "=l"(d) : "l"(a), "l"(b));
    return d;
}

// ---------------- GEMM: C[M,N] = A[M,K] @ B[N,K]^T (NT), fp32 via FFMA2 ----
// 64x64 tile, BK=16, 256 threads, 4x4 microtile. A stored DUPLICATED in smem
// so a 16B load yields two packed broadcast operands {a,a}.
#define GBK 16
#define APITCH 136   // 128 dup floats + pad
__global__ __launch_bounds__(256) void gemm_nt(const float* __restrict__ A,
                                               const float* __restrict__ B,
                                               float* __restrict__ C,
                                               int M, int N, int K) {
    __shared__ float As2[GBK][APITCH];
    __shared__ float Bs[GBK][68];
    const int tid = threadIdx.x;
    const int tx = tid & 15, ty = tid >> 4;
    const int bm = blockIdx.y * 64, bn = blockIdx.x * 64;
    const int lr = tid >> 2;          // 0..63 (tile row to load)
    const int lc = (tid & 3) << 2;    // 0,4,8,12 (k-offset, float4)

    const float* Ap = A + (long)(bm + lr) * K + lc;
    const float* Bp = B + (long)(bn + lr) * K + lc;

    unsigned long long acc2[4][2];
#pragma unroll
    for (int i = 0; i < 4; ++i) { acc2[i][0] = 0ull; acc2[i][1] = 0ull; }

    for (int kt = 0; kt < K; kt += GBK) {
        float4 a4 = *(const float4*)(Ap + kt);
        float4 b4 = *(const float4*)(Bp + kt);
        *(float2*)&As2[lc + 0][2 * lr] = make_float2(a4.x, a4.x);
        *(float2*)&As2[lc + 1][2 * lr] = make_float2(a4.y, a4.y);
        *(float2*)&As2[lc + 2][2 * lr] = make_float2(a4.z, a4.z);
        *(float2*)&As2[lc + 3][2 * lr] = make_float2(a4.w, a4.w);
        Bs[lc + 0][lr] = b4.x; Bs[lc + 1][lr] = b4.y;
        Bs[lc + 2][lr] = b4.z; Bs[lc + 3][lr] = b4.w;
        __syncthreads();
#pragma unroll
        for (int k = 0; k < GBK; ++k) {
            ulonglong2 aA = *(const ulonglong2*)&As2[k][ty * 8];      // {a0,a0},{a1,a1}
            ulonglong2 aB = *(const ulonglong2*)&As2[k][ty * 8 + 4];  // {a2,a2},{a3,a3}
            ulonglong2 bv = *(const ulonglong2*)&Bs[k][tx * 4];       // {b0,b1},{b2,b3}
            ffma2(acc2[0][0], aA.x, bv.x); ffma2(acc2[0][1], aA.x, bv.y);
            ffma2(acc2[1][0], aA.y, bv.x); ffma2(acc2[1][1], aA.y, bv.y);
            ffma2(acc2[2][0], aB.x, bv.x); ffma2(acc2[2][1], aB.x, bv.y);
            ffma2(acc2[3][0], aB.y, bv.x); ffma2(acc2[3][1], aB.y, bv.y);
        }
        __syncthreads();
    }
#pragma unroll
    for (int i = 0; i < 4; ++i) {
        float2 f01 = u2f2(acc2[i][0]);
        float2 f23 = u2f2(acc2[i][1]);
        *(float4*)&C[(long)(bm + ty * 4 + i) * N + bn + tx * 4] =
            make_float4(f01.x, f01.y, f23.x, f23.y);
    }
}

// ---------------- row-wise Mobius transform ----------------
__device__ __forceinline__ float dot4(float4 a, float4 b) {
    return a.x * b.x + a.y * b.y + a.z * b.z + a.w * b.w;
}
__device__ __forceinline__ float warpSum(float v) {
#pragma unroll
    for (int o = 16; o > 0; o >>= 1) v += __shfl_xor_sync(0xffffffffu, v, o);
    return v;
}

__global__ __launch_bounds__(128) void mobius_rows(const float* __restrict__ x,
                                                   const float* __restrict__ mx,
                                                   const float* __restrict__ bias,
                                                   float* __restrict__ out,
                                                   float* __restrict__ hn,
                                                   int with_hn) {
    __shared__ float sa[4], sb[4], sc_[4];
    const int t = threadIdx.x;
    const int w = t >> 5, lane = t & 31;
    const long r = blockIdx.x;

    const float4 xv = ((const float4*)(x + r * EDIM))[t];
    const float4 mv = ((const float4*)(mx + r * EDIM))[t];
    const float4 bv = ((const float4*)bias)[t];

    // batch-1 reduce: x2, m2
    float p1 = warpSum(dot4(xv, xv));
    float p2 = warpSum(dot4(mv, mv));
    if (lane == 0) { sa[w] = p1; sb[w] = p2; }
    __syncthreads();
    float x2 = sa[0] + sa[1] + sa[2] + sa[3];
    float m2 = sb[0] + sb[1] + sb[2] + sb[3];

    float xn = fmaxf(sqrtf(x2), 1e-15f);
    float mn = fmaxf(sqrtf(m2), 1e-15f);
    float u  = fminf(xn, 1.0f - 1e-7f);                 // artanh clip (xn>=0)
    float at = 0.5f * (log1pf(u) - log1pf(-u));
    float tt = tanhf(mn / xn * at);
    float sc = tt / mn;                                 // res = sc * mx

    float4 res = make_float4(mv.x * sc, mv.y * sc, mv.z * sc, mv.w * sc);
    float rn = fmaxf(tt, 1e-15f);
    float pf = (rn > MAXNORM) ? (MAXNORM / rn) : 1.0f;  // project
    res.x *= pf; res.y *= pf; res.z *= pf; res.w *= pf;

    // batch-2 reduce: x2r, y2, xy
    __syncthreads();                 // guard smem reuse
    float q1 = warpSum(dot4(res, res));
    float q2 = warpSum(dot4(bv, bv));
    float q3 = warpSum(dot4(res, bv));
    if (lane == 0) { sa[w] = q1; sb[w] = q2; sc_[w] = q3; }
    __syncthreads();
    float x2r = sa[0] + sa[1] + sa[2] + sa[3];
    float y2  = sb[0] + sb[1] + sb[2] + sb[3];
    float xy  = sc_[0] + sc_[1] + sc_[2] + sc_[3];

    float ca  = 1.0f + 2.0f * xy + y2;
    float cb  = 1.0f - x2r;
    float den = fmaxf(1.0f + 2.0f * xy + x2r * y2, 1e-15f);
    float inv = 1.0f / den;
    float4 o = make_float4((ca * res.x + cb * bv.x) * inv,
                           (ca * res.y + cb * bv.y) * inv,
                           (ca * res.z + cb * bv.z) * inv,
                           (ca * res.w + cb * bv.w) * inv);
    // batch-3 reduce: o2 ; then project
    __syncthreads();
    float q4 = warpSum(dot4(o, o));
    if (lane == 0) { sa[w] = q4; }
    __syncthreads();
    float o2 = sa[0] + sa[1] + sa[2] + sa[3];
    float on = fmaxf(sqrtf(o2), 1e-15f);
    float pf2 = (on > MAXNORM) ? (MAXNORM / on) : 1.0f;
    o.x *= pf2; o.y *= pf2; o.z *= pf2; o.w *= pf2;

    ((float4*)(out + r * EDIM))[t] = o;

    if (with_hn) {
        // per-head (64 elems = 16 threads) squared norm via width-16 shuffles
        float h = dot4(o, o) * (pf2 * pf2) / (pf2 * pf2);  // o already scaled
        h = dot4(o, o);
#pragma unroll
        for (int off = 8; off >= 1; off >>= 1)
            h += __shfl_xor_sync(0xffffffffu, h, off, 16);
        if ((t & 15) == 0) {
            int head = t >> 4;
            int b = (int)(r / SEQ), s = (int)(r % SEQ);
            hn[((long)b * NH + head) * SEQ + s] = fminf(h, 1.0f - 1e-5f);
        }
    }
}

// ---------------- flash-style hyperbolic attention (FFMA2) ----------------
// Block: 64 queries x full key stream, 256 threads (16x16), 4x4 microtiles.
// Q and P stored duplicated ({v,v}) for packed broadcast; K,V pair-packed.
#define QPITCH 136
#define KPITCH 68
#define ASMEM_FLOATS (2 * 64 * QPITCH + 2 * 64 * KPITCH + 128)
#define ASMEM_BYTES  (ASMEM_FLOATS * 4)

__global__ __launch_bounds__(256) void attn_kernel(const float* __restrict__ q,
                                                   const float* __restrict__ k,
                                                   const float* __restrict__ v,
                                                   const float* __restrict__ qn,
                                                   const float* __restrict__ kn,
                                                   float* __restrict__ o) {
    extern __shared__ float sm[];
    float* Qst2 = sm;                          // [DH][QPITCH] dup along query
    float* Kst  = Qst2 + 64 * QPITCH;          // [DH][KPITCH] transposed
    float* Vs   = Kst + 64 * KPITCH;           // [KT][KPITCH]
    float* Pt2  = Vs + 64 * KPITCH;            // [KT][QPITCH] dup along query
    float* qns  = Pt2 + 64 * QPITCH;           // 64
    float* kns  = qns + 64;                    // 64

    const int tid = threadIdx.x;
    const int tx = tid & 15, ty = tid >> 4;
    const int bh = blockIdx.y;                 // 0..B*H-1
    const int b = bh >> 3, h = bh & 7;
    const int q0 = blockIdx.x * 64;

    const float* qbase = q + ((long)b * SEQ + q0) * EDIM + h * DH;

    // load Q tile transposed + duplicated
#pragma unroll
    for (int it = 0; it < 4; ++it) {
        int slot = tid + it * 256;              // 0..1023 float4 slots
        int rr = slot >> 4;                     // 0..63
        int d4 = (slot & 15) << 2;              // 0..60
        float4 t4 = *(const float4*)(qbase + (long)rr * EDIM + d4);
        *(float2*)&Qst2[(d4 + 0) * QPITCH + 2 * rr] = make_float2(t4.x, t4.x);
        *(float2*)&Qst2[(d4 + 1) * QPITCH + 2 * rr] = make_float2(t4.y, t4.y);
        *(float2*)&Qst2[(d4 + 2) * QPITCH + 2 * rr] = make_float2(t4.z, t4.z);
        *(float2*)&Qst2[(d4 + 3) * QPITCH + 2 * rr] = make_float2(t4.w, t4.w);
    }
    if (tid < 64) qns[tid] = qn[((long)b * NH + h) * SEQ + q0 + tid];

    float m[4], l[4];
    unsigned long long O2[4][2];
#pragma unroll
    for (int i = 0; i < 4; ++i) {
        m[i] = -1e30f; l[i] = 0.0f;
        O2[i][0] = 0ull; O2[i][1] = 0ull;
    }

    for (int kt = 0; kt < SEQ; kt += 64) {
        __syncthreads();   // prior-iter PV readers done (also Q visibility, iter 0)
        const float* kbase = k + ((long)b * SEQ + kt) * EDIM + h * DH;
        const float* vbase = v + ((long)b * SEQ + kt) * EDIM + h * DH;
#pragma unroll
        for (int it = 0; it < 4; ++it) {
            int slot = tid + it * 256;
            int rr = slot >> 4;
            int d4 = (slot & 15) << 2;
            float4 t4 = *(const float4*)(kbase + (long)rr * EDIM + d4);
            Kst[(d4 + 0) * KPITCH + rr] = t4.x;
            Kst[(d4 + 1) * KPITCH + rr] = t4.y;
            Kst[(d4 + 2) * KPITCH + rr] = t4.z;
            Kst[(d4 + 3) * KPITCH + rr] = t4.w;
            float4 v4 = *(const float4*)(vbase + (long)rr * EDIM + d4);
            *(float4*)&Vs[rr * KPITCH + d4] = v4;
        }
        if (tid < 64) kns[tid] = kn[((long)b * NH + h) * SEQ + kt + tid];
        __syncthreads();

        // S = Q K^T, packed over key pairs
        unsigned long long acc2[4][2];
#pragma unroll
        for (int i = 0; i < 4; ++i) { acc2[i][0] = 0ull; acc2[i][1] = 0ull; }
#pragma unroll
        for (int d = 0; d < DH; ++d) {
            ulonglong2 aA = *(const ulonglong2*)&Qst2[d * QPITCH + ty * 8];
            ulonglong2 aB = *(const ulonglong2*)&Qst2[d * QPITCH + ty * 8 + 4];
            ulonglong2 bv = *(const ulonglong2*)&Kst[d * KPITCH + tx * 4];
            ffma2(acc2[0][0], aA.x, bv.x); ffma2(acc2[0][1], aA.x, bv.y);
            ffma2(acc2[1][0], aA.y, bv.x); ffma2(acc2[1][1], aA.y, bv.y);
            ffma2(acc2[2][0], aB.x, bv.x); ffma2(acc2[2][1], aB.x, bv.y);
            ffma2(acc2[3][0], aB.y, bv.x); ffma2(acc2[3][1], aB.y, bv.y);
        }

        // hyperbolic score + online softmax
        float p[4][4];
#pragma unroll
        for (int i = 0; i < 4; ++i) {
            float s_[4];
            float2 f01 = u2f2(acc2[i][0]);
            float2 f23 = u2f2(acc2[i][1]);
            s_[0] = f01.x; s_[1] = f01.y; s_[2] = f23.x; s_[3] = f23.y;
            float qnv = qns[ty * 4 + i];
            float oq = 1.0f - qnv;
            float sc[4];
#pragma unroll
            for (int j = 0; j < 4; ++j) {
                float knv = kns[tx * 4 + j];
                float den = oq * (1.0f - knv) + 1e-5f;
                float delta = __fdividef(2.0f * (s_[j] - qnv * knv), den);
                delta = fmaxf(delta, 1e-5f);
                sc[j] = -delta * __frsqrt_rn(delta) * 0.125f;   // -sqrt(delta)/8
            }
            float mx = fmaxf(fmaxf(sc[0], sc[1]), fmaxf(sc[2], sc[3]));
#pragma unroll
            for (int off = 8; off >= 1; off >>= 1)
                mx = fmaxf(mx, __shfl_xor_sync(0xffffffffu, mx, off, 16));
            float mn_ = fmaxf(m[i], mx);
            float alpha = __expf(m[i] - mn_);
            float ps = 0.0f;
#pragma unroll
            for (int j = 0; j < 4; ++j) {
                p[i][j] = __expf(sc[j] - mn_);
                ps += p[i][j];
            }
#pragma unroll
            for (int off = 8; off >= 1; off >>= 1)
                ps += __shfl_xor_sync(0xffffffffu, ps, off, 16);
            l[i] = l[i] * alpha + ps;
            m[i] = mn_;
            unsigned long long a2 = f2u(alpha, alpha);
            O2[i][0] = mul2(O2[i][0], a2);
            O2[i][1] = mul2(O2[i][1], a2);
        }

        // write P duplicated along query dim
#pragma unroll
        for (int i = 0; i < 4; ++i)
#pragma unroll
            for (int j = 0; j < 4; ++j)
                *(float2*)&Pt2[(tx * 4 + j) * QPITCH + ty * 8 + 2 * i] =
                    make_float2(p[i][j], p[i][j]);
        __syncthreads();

        // O += P V, packed over feature pairs
#pragma unroll
        for (int c = 0; c < 64; ++c) {
            ulonglong2 pA = *(const ulonglong2*)&Pt2[c * QPITCH + ty * 8];
            ulonglong2 pB = *(const ulonglong2*)&Pt2[c * QPITCH + ty * 8 + 4];
            ulonglong2 vv = *(const ulonglong2*)&Vs[c * KPITCH + tx * 4];
            ffma2(O2[0][0], pA.x, vv.x); ffma2(O2[0][1], pA.x, vv.y);
            ffma2(O2[1][0], pA.y, vv.x); ffma2(O2[1][1], pA.y, vv.y);
            ffma2(O2[2][0], pB.x, vv.x); ffma2(O2[2][1], pB.x, vv.y);
            ffma2(O2[3][0], pB.y, vv.x); ffma2(O2[3][1], pB.y, vv.y);
        }
    }

    float* obase = o + ((long)b * SEQ + q0) * EDIM + h * DH;
#pragma unroll
    for (int i = 0; i < 4; ++i) {
        float invl = 1.0f / l[i];
        float2 f01 = u2f2(O2[i][0]);
        float2 f23 = u2f2(O2[i][1]);
        *(float4*)(obase + (long)(ty * 4 + i) * EDIM + tx * 4) =
            make_float4(f01.x * invl, f01.y * invl, f23.x * invl, f23.y * invl);
    }
}

// ---------------- launch ----------------
extern "C" void kernel_launch(void* const* d_in, const int* in_sizes, int n_in,
                              void* d_out, int out_size) {
    const float* x  = (const float*)d_in[0];
    const float* Wq = (const float*)d_in[1];
    const float* bq = (const float*)d_in[2];
    const float* Wk = (const float*)d_in[3];
    const float* bk = (const float*)d_in[4];
    const float* Wv = (const float*)d_in[5];
    const float* bv = (const float*)d_in[6];
    const float* Wo = (const float*)d_in[7];
    const float* bo = (const float*)d_in[8];
    float* out = (float*)d_out;

    float *q, *k, *v, *ao, *qn, *kn;
    cudaGetSymbolAddress((void**)&q,  g_q);
    cudaGetSymbolAddress((void**)&k,  g_k);
    cudaGetSymbolAddress((void**)&v,  g_v);
    cudaGetSymbolAddress((void**)&ao, g_ao);
    cudaGetSymbolAddress((void**)&qn, g_qn);
    cudaGetSymbolAddress((void**)&kn, g_kn);

    cudaFuncSetAttribute(attn_kernel, cudaFuncAttributeMaxDynamicSharedMemorySize,
                         ASMEM_BYTES);

    dim3 gg(EDIM / 64, ROWS / 64);          // (8, 128)
    gemm_nt<<<gg, 256>>>(x, Wq, q, ROWS, EDIM, EDIM);
    gemm_nt<<<gg, 256>>>(x, Wk, k, ROWS, EDIM, EDIM);
    gemm_nt<<<gg, 256>>>(x, Wv, v, ROWS, EDIM, EDIM);

    mobius_rows<<<ROWS, 128>>>(x, q, bq, q, qn, 1);
    mobius_rows<<<ROWS, 128>>>(x, k, bk, k, kn, 1);
    mobius_rows<<<ROWS, 128>>>(x, v, bv, v, nullptr, 0);

    dim3 ag(SEQ / 64, BDIM * NH);           // (32, 32)
    attn_kernel<<<ag, 256, ASMEM_BYTES>>>(q, k, v, qn, kn, ao);

    gemm_nt<<<gg, 256>>>(ao, Wo, q, ROWS, EDIM, EDIM);
    mobius_rows<<<ROWS, 128>>>(ao, q, bo, out, nullptr, 0);
}

// round 3
// speedup vs baseline: 1.0006x; 1.0006x over previous
#include <cuda_runtime.h>
#include <math.h>

// Problem constants (fixed by setup_inputs)
#define EDIM 512
#define BDIM 4
#define SEQ  2048
#define NH   8
#define DH   64
#define ROWS (BDIM * SEQ)          // 8192

#define MAXNORM (1.0f - 4e-3f)     // geoopt projx eps for fp32, c=1

// ---------------- scratch (device globals: allocation-free) ----------------
__device__ float g_q[ROWS * EDIM];
__device__ float g_k[ROWS * EDIM];
__device__ float g_v[ROWS * EDIM];
__device__ float g_ao[ROWS * EDIM];
__device__ float g_qn[BDIM * NH * SEQ];
__device__ float g_kn[BDIM * NH * SEQ];

// ---------------- packed f32x2 helpers (Blackwell FFMA2) ----------------
__device__ __forceinline__ unsigned long long f2u(float x, float y) {
    unsigned long long u;
    asm("mov.b64 %0, {%1, %2};" : "=l"(u) : "f"(x), "f"(y));
    return u;
}
__device__ __forceinline__ float2 u2f2(unsigned long long u) {
    float2 f;
    asm("mov.b64 {%0, %1}, %2;" : "=f"(f.x), "=f"(f.y) : "l"(u));
    return f;
}
__device__ __forceinline__ void ffma2(unsigned long long& d,
                                      unsigned long long a, unsigned long long b) {
    asm("fma.rn.f32x2 %0, %1, %2, %0;" : "+l"(d) : "l"(a), "l"(b));
}
__device__ __forceinline__ unsigned long long mul2(unsigned long long a,
                                                   unsigned long long b) {
    unsigned long long d;
    asm("mul.rn.f32x2 %0, %1, %2;" : "=l"(d) : "l"(a), "l"(b));
    return d;
}

// ---------------- GEMM: C[M,N] = A[M,K] @ B[N,K]^T (NT), fp32 via FFMA2 ----
// 64x64 tile, BK=16, 256 threads, 4x4 microtile. A stored DUPLICATED in smem
// so a 16B load yields two packed broadcast operands {a,a}.
#define GBK 16
#define APITCH 136   // 128 dup floats + pad
__global__ __launch_bounds__(256) void gemm_nt(const float* __restrict__ A,
                                               const float* __restrict__ B,
                                               float* __restrict__ C,
                                               int M, int N, int K) {
    __shared__ float As2[GBK][APITCH];
    __shared__ float Bs[GBK][68];
    const int tid = threadIdx.x;
    const int tx = tid & 15, ty = tid >> 4;
    const int bm = blockIdx.y * 64, bn = blockIdx.x * 64;
    const int lr = tid >> 2;          // 0..63 (tile row to load)
    const int lc = (tid & 3) << 2;    // 0,4,8,12 (k-offset, float4)

    const float* Ap = A + (long)(bm + lr) * K + lc;
    const float* Bp = B + (long)(bn + lr) * K + lc;

    unsigned long long acc2[4][2];
#pragma unroll
    for (int i = 0; i < 4; ++i) { acc2[i][0] = 0ull; acc2[i][1] = 0ull; }

    for (int kt = 0; kt < K; kt += GBK) {
        float4 a4 = *(const float4*)(Ap + kt);
        float4 b4 = *(const float4*)(Bp + kt);
        *(float2*)&As2[lc + 0][2 * lr] = make_float2(a4.x, a4.x);
        *(float2*)&As2[lc + 1][2 * lr] = make_float2(a4.y, a4.y);
        *(float2*)&As2[lc + 2][2 * lr] = make_float2(a4.z, a4.z);
        *(float2*)&As2[lc + 3][2 * lr] = make_float2(a4.w, a4.w);
        Bs[lc + 0][lr] = b4.x; Bs[lc + 1][lr] = b4.y;
        Bs[lc + 2][lr] = b4.z; Bs[lc + 3][lr] = b4.w;
        __syncthreads();
#pragma unroll
        for (int k = 0; k < GBK; ++k) {
            ulonglong2 aA = *(const ulonglong2*)&As2[k][ty * 8];      // {a0,a0},{a1,a1}
            ulonglong2 aB = *(const ulonglong2*)&As2[k][ty * 8 + 4];  // {a2,a2},{a3,a3}
            ulonglong2 bv = *(const ulonglong2*)&Bs[k][tx * 4];       // {b0,b1},{b2,b3}
            ffma2(acc2[0][0], aA.x, bv.x); ffma2(acc2[0][1], aA.x, bv.y);
            ffma2(acc2[1][0], aA.y, bv.x); ffma2(acc2[1][1], aA.y, bv.y);
            ffma2(acc2[2][0], aB.x, bv.x); ffma2(acc2[2][1], aB.x, bv.y);
            ffma2(acc2[3][0], aB.y, bv.x); ffma2(acc2[3][1], aB.y, bv.y);
        }
        __syncthreads();
    }
#pragma unroll
    for (int i = 0; i < 4; ++i) {
        float2 f01 = u2f2(acc2[i][0]);
        float2 f23 = u2f2(acc2[i][1]);
        *(float4*)&C[(long)(bm + ty * 4 + i) * N + bn + tx * 4] =
            make_float4(f01.x, f01.y, f23.x, f23.y);
    }
}

// ---------------- row-wise Mobius transform ----------------
__device__ __forceinline__ float dot4(float4 a, float4 b) {
    return a.x * b.x + a.y * b.y + a.z * b.z + a.w * b.w;
}
__device__ __forceinline__ float warpSum(float v) {
#pragma unroll
    for (int o = 16; o > 0; o >>= 1) v += __shfl_xor_sync(0xffffffffu, v, o);
    return v;
}

__global__ __launch_bounds__(128) void mobius_rows(const float* __restrict__ x,
                                                   const float* __restrict__ mx,
                                                   const float* __restrict__ bias,
                                                   float* __restrict__ out,
                                                   float* __restrict__ hn,
                                                   int with_hn) {
    __shared__ float sa[4], sb[4], sc_[4];
    const int t = threadIdx.x;
    const int w = t >> 5, lane = t & 31;
    const long r = blockIdx.x;

    const float4 xv = ((const float4*)(x + r * EDIM))[t];
    const float4 mv = ((const float4*)(mx + r * EDIM))[t];
    const float4 bv = ((const float4*)bias)[t];

    // batch-1 reduce: x2, m2
    float p1 = warpSum(dot4(xv, xv));
    float p2 = warpSum(dot4(mv, mv));
    if (lane == 0) { sa[w] = p1; sb[w] = p2; }
    __syncthreads();
    float x2 = sa[0] + sa[1] + sa[2] + sa[3];
    float m2 = sb[0] + sb[1] + sb[2] + sb[3];

    float xn = fmaxf(sqrtf(x2), 1e-15f);
    float mn = fmaxf(sqrtf(m2), 1e-15f);
    float u  = fminf(xn, 1.0f - 1e-7f);                 // artanh clip (xn>=0)
    float at = 0.5f * (log1pf(u) - log1pf(-u));
    float tt = tanhf(mn / xn * at);
    float sc = tt / mn;                                 // res = sc * mx

    float4 res = make_float4(mv.x * sc, mv.y * sc, mv.z * sc, mv.w * sc);
    float rn = fmaxf(tt, 1e-15f);
    float pf = (rn > MAXNORM) ? (MAXNORM / rn) : 1.0f;  // project
    res.x *= pf; res.y *= pf; res.z *= pf; res.w *= pf;

    // batch-2 reduce: x2r, y2, xy
    __syncthreads();                 // guard smem reuse
    float q1 = warpSum(dot4(res, res));
    float q2 = warpSum(dot4(bv, bv));
    float q3 = warpSum(dot4(res, bv));
    if (lane == 0) { sa[w] = q1; sb[w] = q2; sc_[w] = q3; }
    __syncthreads();
    float x2r = sa[0] + sa[1] + sa[2] + sa[3];
    float y2  = sb[0] + sb[1] + sb[2] + sb[3];
    float xy  = sc_[0] + sc_[1] + sc_[2] + sc_[3];

    float ca  = 1.0f + 2.0f * xy + y2;
    float cb  = 1.0f - x2r;
    float den = fmaxf(1.0f + 2.0f * xy + x2r * y2, 1e-15f);
    float inv = 1.0f / den;
    float4 o = make_float4((ca * res.x + cb * bv.x) * inv,
                           (ca * res.y + cb * bv.y) * inv,
                           (ca * res.z + cb * bv.z) * inv,
                           (ca * res.w + cb * bv.w) * inv);
    // batch-3 reduce: o2 ; then project
    __syncthreads();
    float q4 = warpSum(dot4(o, o));
    if (lane == 0) { sa[w] = q4; }
    __syncthreads();
    float o2 = sa[0] + sa[1] + sa[2] + sa[3];
    float on = fmaxf(sqrtf(o2), 1e-15f);
    float pf2 = (on > MAXNORM) ? (MAXNORM / on) : 1.0f;
    o.x *= pf2; o.y *= pf2; o.z *= pf2; o.w *= pf2;

    ((float4*)(out + r * EDIM))[t] = o;

    if (with_hn) {
        // per-head (64 elems = 16 threads) squared norm via width-16 shuffles
        float h = dot4(o, o) * (pf2 * pf2) / (pf2 * pf2);  // o already scaled
        h = dot4(o, o);
#pragma unroll
        for (int off = 8; off >= 1; off >>= 1)
            h += __shfl_xor_sync(0xffffffffu, h, off, 16);
        if ((t & 15) == 0) {
            int head = t >> 4;
            int b = (int)(r / SEQ), s = (int)(r % SEQ);
            hn[((long)b * NH + head) * SEQ + s] = fminf(h, 1.0f - 1e-5f);
        }
    }
}

// ---------------- flash-style hyperbolic attention (FFMA2) ----------------
// Block: 64 queries x full key stream, 256 threads (16x16), 4x4 microtiles.
// Q and P stored duplicated ({v,v}) for packed broadcast; K,V pair-packed.
#define QPITCH 136
#define KPITCH 68
#define ASMEM_FLOATS (2 * 64 * QPITCH + 2 * 64 * KPITCH + 128)
#define ASMEM_BYTES  (ASMEM_FLOATS * 4)

__global__ __launch_bounds__(256) void attn_kernel(const float* __restrict__ q,
                                                   const float* __restrict__ k,
                                                   const float* __restrict__ v,
                                                   const float* __restrict__ qn,
                                                   const float* __restrict__ kn,
                                                   float* __restrict__ o) {
    extern __shared__ float sm[];
    float* Qst2 = sm;                          // [DH][QPITCH] dup along query
    float* Kst  = Qst2 + 64 * QPITCH;          // [DH][KPITCH] transposed
    float* Vs   = Kst + 64 * KPITCH;           // [KT][KPITCH]
    float* Pt2  = Vs + 64 * KPITCH;            // [KT][QPITCH] dup along query
    float* qns  = Pt2 + 64 * QPITCH;           // 64
    float* kns  = qns + 64;                    // 64

    const int tid = threadIdx.x;
    const int tx = tid & 15, ty = tid >> 4;
    const int bh = blockIdx.y;                 // 0..B*H-1
    const int b = bh >> 3, h = bh & 7;
    const int q0 = blockIdx.x * 64;

    const float* qbase = q + ((long)b * SEQ + q0) * EDIM + h * DH;

    // load Q tile transposed + duplicated
#pragma unroll
    for (int it = 0; it < 4; ++it) {
        int slot = tid + it * 256;              // 0..1023 float4 slots
        int rr = slot >> 4;                     // 0..63
        int d4 = (slot & 15) << 2;              // 0..60
        float4 t4 = *(const float4*)(qbase + (long)rr * EDIM + d4);
        *(float2*)&Qst2[(d4 + 0) * QPITCH + 2 * rr] = make_float2(t4.x, t4.x);
        *(float2*)&Qst2[(d4 + 1) * QPITCH + 2 * rr] = make_float2(t4.y, t4.y);
        *(float2*)&Qst2[(d4 + 2) * QPITCH + 2 * rr] = make_float2(t4.z, t4.z);
        *(float2*)&Qst2[(d4 + 3) * QPITCH + 2 * rr] = make_float2(t4.w, t4.w);
    }
    if (tid < 64) qns[tid] = qn[((long)b * NH + h) * SEQ + q0 + tid];

    float m[4], l[4];
    unsigned long long O2[4][2];
#pragma unroll
    for (int i = 0; i < 4; ++i) {
        m[i] = -1e30f; l[i] = 0.0f;
        O2[i][0] = 0ull; O2[i][1] = 0ull;
    }

    for (int kt = 0; kt < SEQ; kt += 64) {
        __syncthreads();   // prior-iter PV readers done (also Q visibility, iter 0)
        const float* kbase = k + ((long)b * SEQ + kt) * EDIM + h * DH;
        const float* vbase = v + ((long)b * SEQ + kt) * EDIM + h * DH;
#pragma unroll
        for (int it = 0; it < 4; ++it) {
            int slot = tid + it * 256;
            int rr = slot >> 4;
            int d4 = (slot & 15) << 2;
            float4 t4 = *(const float4*)(kbase + (long)rr * EDIM + d4);
            Kst[(d4 + 0) * KPITCH + rr] = t4.x;
            Kst[(d4 + 1) * KPITCH + rr] = t4.y;
            Kst[(d4 + 2) * KPITCH + rr] = t4.z;
            Kst[(d4 + 3) * KPITCH + rr] = t4.w;
            float4 v4 = *(const float4*)(vbase + (long)rr * EDIM + d4);
            *(float4*)&Vs[rr * KPITCH + d4] = v4;
        }
        if (tid < 64) kns[tid] = kn[((long)b * NH + h) * SEQ + kt + tid];
        __syncthreads();

        // S = Q K^T, packed over key pairs
        unsigned long long acc2[4][2];
#pragma unroll
        for (int i = 0; i < 4; ++i) { acc2[i][0] = 0ull; acc2[i][1] = 0ull; }
#pragma unroll
        for (int d = 0; d < DH; ++d) {
            ulonglong2 aA = *(const ulonglong2*)&Qst2[d * QPITCH + ty * 8];
            ulonglong2 aB = *(const ulonglong2*)&Qst2[d * QPITCH + ty * 8 + 4];
            ulonglong2 bv = *(const ulonglong2*)&Kst[d * KPITCH + tx * 4];
            ffma2(acc2[0][0], aA.x, bv.x); ffma2(acc2[0][1], aA.x, bv.y);
            ffma2(acc2[1][0], aA.y, bv.x); ffma2(acc2[1][1], aA.y, bv.y);
            ffma2(acc2[2][0], aB.x, bv.x); ffma2(acc2[2][1], aB.x, bv.y);
            ffma2(acc2[3][0], aB.y, bv.x); ffma2(acc2[3][1], aB.y, bv.y);
        }

        // hyperbolic score + online softmax
        float p[4][4];
#pragma unroll
        for (int i = 0; i < 4; ++i) {
            float s_[4];
            float2 f01 = u2f2(acc2[i][0]);
            float2 f23 = u2f2(acc2[i][1]);
            s_[0] = f01.x; s_[1] = f01.y; s_[2] = f23.x; s_[3] = f23.y;
            float qnv = qns[ty * 4 + i];
            float oq = 1.0f - qnv;
            float sc[4];
#pragma unroll
            for (int j = 0; j < 4; ++j) {
                float knv = kns[tx * 4 + j];
                float den = oq * (1.0f - knv) + 1e-5f;
                float delta = __fdividef(2.0f * (s_[j] - qnv * knv), den);
                delta = fmaxf(delta, 1e-5f);
                sc[j] = -delta * __frsqrt_rn(delta) * 0.125f;   // -sqrt(delta)/8
            }
            float mx = fmaxf(fmaxf(sc[0], sc[1]), fmaxf(sc[2], sc[3]));
#pragma unroll
            for (int off = 8; off >= 1; off >>= 1)
                mx = fmaxf(mx, __shfl_xor_sync(0xffffffffu, mx, off, 16));
            float mn_ = fmaxf(m[i], mx);
            float alpha = __expf(m[i] - mn_);
            float ps = 0.0f;
#pragma unroll
            for (int j = 0; j < 4; ++j) {
                p[i][j] = __expf(sc[j] - mn_);
                ps += p[i][j];
            }
#pragma unroll
            for (int off = 8; off >= 1; off >>= 1)
                ps += __shfl_xor_sync(0xffffffffu, ps, off, 16);
            l[i] = l[i] * alpha + ps;
            m[i] = mn_;
            unsigned long long a2 = f2u(alpha, alpha);
            O2[i][0] = mul2(O2[i][0], a2);
            O2[i][1] = mul2(O2[i][1], a2);
        }

        // write P duplicated along query dim
#pragma unroll
        for (int i = 0; i < 4; ++i)
#pragma unroll
            for (int j = 0; j < 4; ++j)
                *(float2*)&Pt2[(tx * 4 + j) * QPITCH + ty * 8 + 2 * i] =
                    make_float2(p[i][j], p[i][j]);
        __syncthreads();

        // O += P V, packed over feature pairs
#pragma unroll
        for (int c = 0; c < 64; ++c) {
            ulonglong2 pA = *(const ulonglong2*)&Pt2[c * QPITCH + ty * 8];
            ulonglong2 pB = *(const ulonglong2*)&Pt2[c * QPITCH + ty * 8 + 4];
            ulonglong2 vv = *(const ulonglong2*)&Vs[c * KPITCH + tx * 4];
            ffma2(O2[0][0], pA.x, vv.x); ffma2(O2[0][1], pA.x, vv.y);
            ffma2(O2[1][0], pA.y, vv.x); ffma2(O2[1][1], pA.y, vv.y);
            ffma2(O2[2][0], pB.x, vv.x); ffma2(O2[2][1], pB.x, vv.y);
            ffma2(O2[3][0], pB.y, vv.x); ffma2(O2[3][1], pB.y, vv.y);
        }
    }

    float* obase = o + ((long)b * SEQ + q0) * EDIM + h * DH;
#pragma unroll
    for (int i = 0; i < 4; ++i) {
        float invl = 1.0f / l[i];
        float2 f01 = u2f2(O2[i][0]);
        float2 f23 = u2f2(O2[i][1]);
        *(float4*)(obase + (long)(ty * 4 + i) * EDIM + tx * 4) =
            make_float4(f01.x * invl, f01.y * invl, f23.x * invl, f23.y * invl);
    }
}

// ---------------- launch ----------------
extern "C" void kernel_launch(void* const* d_in, const int* in_sizes, int n_in,
                              void* d_out, int out_size) {
    const float* x  = (const float*)d_in[0];
    const float* Wq = (const float*)d_in[1];
    const float* bq = (const float*)d_in[2];
    const float* Wk = (const float*)d_in[3];
    const float* bk = (const float*)d_in[4];
    const float* Wv = (const float*)d_in[5];
    const float* bv = (const float*)d_in[6];
    const float* Wo = (const float*)d_in[7];
    const float* bo = (const float*)d_in[8];
    float* out = (float*)d_out;

    float *q, *k, *v, *ao, *qn, *kn;
    cudaGetSymbolAddress((void**)&q,  g_q);
    cudaGetSymbolAddress((void**)&k,  g_k);
    cudaGetSymbolAddress((void**)&v,  g_v);
    cudaGetSymbolAddress((void**)&ao, g_ao);
    cudaGetSymbolAddress((void**)&qn, g_qn);
    cudaGetSymbolAddress((void**)&kn, g_kn);

    cudaFuncSetAttribute(attn_kernel, cudaFuncAttributeMaxDynamicSharedMemorySize,
                         ASMEM_BYTES);

    dim3 gg(EDIM / 64, ROWS / 64);          // (8, 128)
    gemm_nt<<<gg, 256>>>(x, Wq, q, ROWS, EDIM, EDIM);
    gemm_nt<<<gg, 256>>>(x, Wk, k, ROWS, EDIM, EDIM);
    gemm_nt<<<gg, 256>>>(x, Wv, v, ROWS, EDIM, EDIM);

    mobius_rows<<<ROWS, 128>>>(x, q, bq, q, qn, 1);
    mobius_rows<<<ROWS, 128>>>(x, k, bk, k, kn, 1);
    mobius_rows<<<ROWS, 128>>>(x, v, bv, v, nullptr, 0);

    dim3 ag(SEQ / 64, BDIM * NH);           // (32, 32)
    attn_kernel<<<ag, 256, ASMEM_BYTES>>>(q, k, v, qn, kn, ao);

    gemm_nt<<<gg, 256>>>(ao, Wo, q, ROWS, EDIM, EDIM);
    mobius_rows<<<ROWS, 128>>>(ao, q, bo, out, nullptr, 0);
}

// round 4
// speedup vs baseline: 2.0778x; 2.0764x over previous
#include <cuda_runtime.h>
#include <cuda_bf16.h>
#include <math.h>

#define EDIM 512
#define BDIM 4
#define SEQ  2048
#define NH   8
#define DH   64
#define ROWS (BDIM*SEQ)
#define BH   (BDIM*NH)
#define KCAT 1536
#define MAXNORM (1.0f - 4e-3f)

// ---------------- scratch ----------------
__device__ float g_q[ROWS*EDIM];
__device__ float g_k[ROWS*EDIM];
__device__ float g_v[ROWS*EDIM];
__device__ float g_ao[ROWS*EDIM];
__device__ float g_st[ROWS*EDIM];
__device__ __nv_bfloat16 g_xcat[(long)ROWS*KCAT];
__device__ __nv_bfloat16 g_wcat[4L*EDIM*KCAT];
__device__ float g_qn[BH*SEQ];
__device__ float g_kn[BH*SEQ];

// ---------------- mma helpers ----------------
__device__ __forceinline__ void ldmA(unsigned r[4], const __nv_bfloat16* p0, int pitch) {
    int l = threadIdx.x & 31;
    unsigned a = (unsigned)__cvta_generic_to_shared(p0 + (l & 15) * pitch + ((l >> 4) << 3));
    asm volatile("ldmatrix.sync.aligned.m8n8.x4.shared.b16 {%0,%1,%2,%3}, [%4];"
                 : "=r"(r[0]), "=r"(r[1]), "=r"(r[2]), "=r"(r[3]) : "r"(a));
}
// B row-major [n][k]: returns b0,b1 of n-tile0 and n-tile1 (16 n-rows)
__device__ __forceinline__ void ldmB2(unsigned r[4], const __nv_bfloat16* p0, int pitch) {
    int l = threadIdx.x & 31;
    unsigned a = (unsigned)__cvta_generic_to_shared(p0 + ((l & 7) + ((l >> 4) << 3)) * pitch + (l & 8));
    asm volatile("ldmatrix.sync.aligned.m8n8.x4.shared.b16 {%0,%1,%2,%3}, [%4];"
                 : "=r"(r[0]), "=r"(r[1]), "=r"(r[2]), "=r"(r[3]) : "r"(a));
}
__device__ __forceinline__ void mmabf(float c[4], const unsigned a[4], unsigned b0, unsigned b1) {
    asm volatile("mma.sync.aligned.m16n8k16.row.col.f32.bf16.bf16.f32 "
                 "{%0,%1,%2,%3},{%4,%5,%6,%7},{%8,%9},{%0,%1,%2,%3};"
                 : "+f"(c[0]), "+f"(c[1]), "+f"(c[2]), "+f"(c[3])
                 : "r"(a[0]), "r"(a[1]), "r"(a[2]), "r"(a[3]), "r"(b0), "r"(b1));
}
__device__ __forceinline__ unsigned packbf(float lo, float hi) {
    unsigned r;
    asm("cvt.rn.bf16x2.f32 %0, %1, %2;" : "=r"(r) : "f"(hi), "f"(lo));
    return r;
}

// ---------------- split_cat: fp32 -> bf16 [hi|hi|lo](pat0) / [hi|lo|hi](pat1) ----
__global__ __launch_bounds__(256) void split_cat(const float* __restrict__ src,
                                                 __nv_bfloat16* __restrict__ dst,
                                                 long n2, int pat) {
    long i = (long)blockIdx.x * blockDim.x + threadIdx.x;
    if (i >= n2) return;
    long e = i * 2;
    long r = e >> 9; int c = (int)(e & 511);
    float v0 = src[e], v1 = src[e + 1];
    __nv_bfloat16 h0 = __float2bfloat16_rn(v0), h1 = __float2bfloat16_rn(v1);
    __nv_bfloat16 l0 = __float2bfloat16_rn(v0 - __bfloat162float(h0));
    __nv_bfloat16 l1 = __float2bfloat16_rn(v1 - __bfloat162float(h1));
    __nv_bfloat16* p = dst + r * KCAT + c;
    p[0] = h0; p[1] = h1;
    if (pat == 0) { p[512] = h0; p[513] = h1; p[1024] = l0; p[1025] = l1; }
    else          { p[512] = l0; p[513] = l1; p[1024] = h0; p[1025] = h1; }
}

// ---------------- bf16 NT GEMM: C fp32 = A[M,K] @ B[N,K]^T, 128x128, BK=32 ----
__global__ __launch_bounds__(256) void gemm_bf16(const __nv_bfloat16* __restrict__ A,
                                                 const __nv_bfloat16* __restrict__ B,
                                                 float* __restrict__ C,
                                                 int M, int N, int K) {
    __shared__ __nv_bfloat16 As[128][40];
    __shared__ __nv_bfloat16 Bs[128][40];
    const int tid = threadIdx.x, lane = tid & 31, wid = tid >> 5;
    const int wm = wid & 3, wn = wid >> 2;
    const int bm = blockIdx.y * 128, bn = blockIdx.x * 128;

    float acc[2][8][4] = {};
    for (int kt = 0; kt < K; kt += 32) {
#pragma unroll
        for (int i = 0; i < 2; ++i) {
            int slot = tid + i * 256;
            int row = slot >> 2, ch = (slot & 3) * 8;
            *(uint4*)&As[row][ch] = *(const uint4*)&A[(long)(bm + row) * K + kt + ch];
            *(uint4*)&Bs[row][ch] = *(const uint4*)&B[(long)(bn + row) * K + kt + ch];
        }
        __syncthreads();
#pragma unroll
        for (int c = 0; c < 2; ++c) {
            unsigned a0[4], a1[4];
            ldmA(a0, &As[wm * 32][c * 16], 40);
            ldmA(a1, &As[wm * 32 + 16][c * 16], 40);
#pragma unroll
            for (int np = 0; np < 4; ++np) {
                unsigned b[4];
                ldmB2(b, &Bs[wn * 64 + np * 16][c * 16], 40);
                mmabf(acc[0][2 * np], a0, b[0], b[1]);
                mmabf(acc[0][2 * np + 1], a0, b[2], b[3]);
                mmabf(acc[1][2 * np], a1, b[0], b[1]);
                mmabf(acc[1][2 * np + 1], a1, b[2], b[3]);
            }
        }
        __syncthreads();
    }
#pragma unroll
    for (int mt = 0; mt < 2; ++mt) {
        int r0 = bm + wm * 32 + mt * 16 + (lane >> 2);
#pragma unroll
        for (int nt = 0; nt < 8; ++nt) {
            int cc = bn + wn * 64 + nt * 8 + 2 * (lane & 3);
            *(float2*)&C[(long)r0 * N + cc] = make_float2(acc[mt][nt][0], acc[mt][nt][1]);
            *(float2*)&C[(long)(r0 + 8) * N + cc] = make_float2(acc[mt][nt][2], acc[mt][nt][3]);
        }
    }
}

// ---------------- row-wise Mobius transform (R1 version) ----------------
__device__ __forceinline__ float dot4(float4 a, float4 b) {
    return a.x * b.x + a.y * b.y + a.z * b.z + a.w * b.w;
}
__device__ __forceinline__ float warpSum(float v) {
#pragma unroll
    for (int o = 16; o > 0; o >>= 1) v += __shfl_xor_sync(0xffffffffu, v, o);
    return v;
}
__global__ __launch_bounds__(128) void mobius_rows(const float* __restrict__ x,
                                                   const float* __restrict__ mx,
                                                   const float* __restrict__ bias,
                                                   float* __restrict__ out,
                                                   float* __restrict__ hn, int with_hn) {
    __shared__ float sa[4], sb[4], sc_[4];
    const int t = threadIdx.x, w = t >> 5, lane = t & 31;
    const long r = blockIdx.x;
    const float4 xv = ((const float4*)(x + r * EDIM))[t];
    const float4 mv = ((const float4*)(mx + r * EDIM))[t];
    const float4 bv = ((const float4*)bias)[t];

    float p1 = warpSum(dot4(xv, xv)), p2 = warpSum(dot4(mv, mv));
    if (lane == 0) { sa[w] = p1; sb[w] = p2; }
    __syncthreads();
    float x2 = sa[0] + sa[1] + sa[2] + sa[3];
    float m2 = sb[0] + sb[1] + sb[2] + sb[3];

    float xn = fmaxf(sqrtf(x2), 1e-15f);
    float mn = fmaxf(sqrtf(m2), 1e-15f);
    float u = fminf(xn, 1.0f - 1e-7f);
    float at = 0.5f * (log1pf(u) - log1pf(-u));
    float tt = tanhf(mn / xn * at);
    float sc = tt / mn;
    float4 res = make_float4(mv.x * sc, mv.y * sc, mv.z * sc, mv.w * sc);
    float rn = fmaxf(tt, 1e-15f);
    float pf = (rn > MAXNORM) ? (MAXNORM / rn) : 1.0f;
    res.x *= pf; res.y *= pf; res.z *= pf; res.w *= pf;

    __syncthreads();
    float q1 = warpSum(dot4(res, res)), q2 = warpSum(dot4(bv, bv)), q3 = warpSum(dot4(res, bv));
    if (lane == 0) { sa[w] = q1; sb[w] = q2; sc_[w] = q3; }
    __syncthreads();
    float x2r = sa[0] + sa[1] + sa[2] + sa[3];
    float y2 = sb[0] + sb[1] + sb[2] + sb[3];
    float xy = sc_[0] + sc_[1] + sc_[2] + sc_[3];
    float ca = 1.0f + 2.0f * xy + y2, cb = 1.0f - x2r;
    float den = fmaxf(1.0f + 2.0f * xy + x2r * y2, 1e-15f);
    float inv = 1.0f / den;
    float4 o = make_float4((ca * res.x + cb * bv.x) * inv, (ca * res.y + cb * bv.y) * inv,
                           (ca * res.z + cb * bv.z) * inv, (ca * res.w + cb * bv.w) * inv);
    __syncthreads();
    float q4 = warpSum(dot4(o, o));
    if (lane == 0) sa[w] = q4;
    __syncthreads();
    float o2 = sa[0] + sa[1] + sa[2] + sa[3];
    float on = fmaxf(sqrtf(o2), 1e-15f);
    float pf2 = (on > MAXNORM) ? (MAXNORM / on) : 1.0f;
    o.x *= pf2; o.y *= pf2; o.z *= pf2; o.w *= pf2;
    ((float4*)(out + r * EDIM))[t] = o;

    if (with_hn) {
        float h = dot4(o, o);
#pragma unroll
        for (int off = 8; off >= 1; off >>= 1) h += __shfl_xor_sync(0xffffffffu, h, off, 16);
        if ((t & 15) == 0) {
            int b = (int)(r / SEQ), s = (int)(r % SEQ);
            hn[((long)b * NH + (t >> 4)) * SEQ + s] = fminf(h, 1.0f - 1e-5f);
        }
    }
}

// ---------------- flash hyperbolic attention, bf16 split MMA ----------------
#define QP 200
#define VP 72
#define ASMB (64*QP*2*2 + 64*VP*2*2 + 512)

__device__ __forceinline__ float qred_max(float v) {
    v = fmaxf(v, __shfl_xor_sync(0xffffffffu, v, 1));
    return fmaxf(v, __shfl_xor_sync(0xffffffffu, v, 2));
}
__device__ __forceinline__ float qred_sum(float v) {
    v += __shfl_xor_sync(0xffffffffu, v, 1);
    return v + __shfl_xor_sync(0xffffffffu, v, 2);
}

__global__ __launch_bounds__(128) void attn_mma(const float* __restrict__ q,
                                                const float* __restrict__ k,
                                                const float* __restrict__ v,
                                                const float* __restrict__ qn,
                                                const float* __restrict__ kn,
                                                float* __restrict__ o) {
    extern __shared__ char sm8[];
    __nv_bfloat16* Qs = (__nv_bfloat16*)sm8;       // [64][QP] = [qhi|qhi|qlo]
    __nv_bfloat16* Ks = Qs + 64 * QP;              // [64][QP] = [khi|klo|khi]
    __nv_bfloat16* Vh = Ks + 64 * QP;              // [dh][VP] transposed hi
    __nv_bfloat16* Vl = Vh + 64 * VP;              // transposed lo
    float* qns = (float*)(Vl + 64 * VP);
    float* kns = qns + 64;

    const int tid = threadIdx.x, lane = tid & 31, wid = tid >> 5;
    const int bh = blockIdx.y, b = bh >> 3, h = bh & 7;
    const int q0 = blockIdx.x * 64;

    const float* qb = q + ((long)b * SEQ + q0) * EDIM + h * DH;
#pragma unroll
    for (int it = 0; it < 8; ++it) {
        int slot = tid + it * 128;
        int r = slot >> 4, c4 = (slot & 15) * 4;
        float4 t4 = *(const float4*)(qb + (long)r * EDIM + c4);
        float f[4] = {t4.x, t4.y, t4.z, t4.w};
#pragma unroll
        for (int j = 0; j < 4; ++j) {
            __nv_bfloat16 hi = __float2bfloat16_rn(f[j]);
            __nv_bfloat16 lo = __float2bfloat16_rn(f[j] - __bfloat162float(hi));
            Qs[r * QP + c4 + j] = hi;
            Qs[r * QP + 64 + c4 + j] = hi;
            Qs[r * QP + 128 + c4 + j] = lo;
        }
    }
    if (tid < 64) qns[tid] = qn[(long)bh * SEQ + q0 + tid];
    __syncthreads();
    const float qn0 = qns[wid * 16 + (lane >> 2)];
    const float qn1 = qns[wid * 16 + (lane >> 2) + 8];

    float m0 = -1e30f, m1 = -1e30f, l0 = 0.0f, l1 = 0.0f;
    float O[8][4] = {};

    for (int kt = 0; kt < SEQ; kt += 64) {
        __syncthreads();
        const float* kb = k + ((long)b * SEQ + kt) * EDIM + h * DH;
        const float* vb = v + ((long)b * SEQ + kt) * EDIM + h * DH;
#pragma unroll
        for (int it = 0; it < 8; ++it) {
            int slot = tid + it * 128;
            int r = slot >> 4, c4 = (slot & 15) * 4;
            float4 t4 = *(const float4*)(kb + (long)r * EDIM + c4);
            float f[4] = {t4.x, t4.y, t4.z, t4.w};
#pragma unroll
            for (int j = 0; j < 4; ++j) {
                __nv_bfloat16 hi = __float2bfloat16_rn(f[j]);
                __nv_bfloat16 lo = __float2bfloat16_rn(f[j] - __bfloat162float(hi));
                Ks[r * QP + c4 + j] = hi;
                Ks[r * QP + 64 + c4 + j] = lo;
                Ks[r * QP + 128 + c4 + j] = hi;
            }
            float4 v4 = *(const float4*)(vb + (long)r * EDIM + c4);
            float g[4] = {v4.x, v4.y, v4.z, v4.w};
#pragma unroll
            for (int j = 0; j < 4; ++j) {
                __nv_bfloat16 hi = __float2bfloat16_rn(g[j]);
                __nv_bfloat16 lo = __float2bfloat16_rn(g[j] - __bfloat162float(hi));
                Vh[(c4 + j) * VP + r] = hi;
                Vl[(c4 + j) * VP + r] = lo;
            }
        }
        if (tid < 64) kns[tid] = kn[(long)bh * SEQ + kt + tid];
        __syncthreads();

        // S = Qcat @ Kcat^T  (K_eff = 192)
        float c[8][4] = {};
#pragma unroll
        for (int cs = 0; cs < 12; ++cs) {
            unsigned a[4];
            ldmA(a, Qs + wid * 16 * QP + cs * 16, QP);
#pragma unroll
            for (int np = 0; np < 4; ++np) {
                unsigned bb[4];
                ldmB2(bb, Ks + np * 16 * QP + cs * 16, QP);
                mmabf(c[2 * np], a, bb[0], bb[1]);
                mmabf(c[2 * np + 1], a, bb[2], bb[3]);
            }
        }

        // scores (in place) + online softmax
#pragma unroll
        for (int nt = 0; nt < 8; ++nt) {
#pragma unroll
            for (int e = 0; e < 4; ++e) {
                int col = nt * 8 + 2 * (lane & 3) + (e & 1);
                float knv = kns[col];
                float qq = (e < 2) ? qn0 : qn1;
                float d_ = __fdividef(2.0f * (c[nt][e] - qq * knv),
                                      (1.0f - qq) * (1.0f - knv) + 1e-5f);
                d_ = fmaxf(d_, 1e-5f);
                c[nt][e] = -d_ * __frsqrt_rn(d_) * 0.125f;
            }
        }
        float mx0 = -1e30f, mx1 = -1e30f;
#pragma unroll
        for (int nt = 0; nt < 8; ++nt) {
            mx0 = fmaxf(mx0, fmaxf(c[nt][0], c[nt][1]));
            mx1 = fmaxf(mx1, fmaxf(c[nt][2], c[nt][3]));
        }
        mx0 = qred_max(mx0); mx1 = qred_max(mx1);
        float nm0 = fmaxf(m0, mx0), nm1 = fmaxf(m1, mx1);
        float al0 = __expf(m0 - nm0), al1 = __expf(m1 - nm1);
        float s0 = 0.0f, s1 = 0.0f;
#pragma unroll
        for (int nt = 0; nt < 8; ++nt) {
            c[nt][0] = __expf(c[nt][0] - nm0); s0 += c[nt][0];
            c[nt][1] = __expf(c[nt][1] - nm0); s0 += c[nt][1];
            c[nt][2] = __expf(c[nt][2] - nm1); s1 += c[nt][2];
            c[nt][3] = __expf(c[nt][3] - nm1); s1 += c[nt][3];
        }
        s0 = qred_sum(s0); s1 = qred_sum(s1);
        l0 = l0 * al0 + s0; l1 = l1 * al1 + s1; m0 = nm0; m1 = nm1;
#pragma unroll
        for (int nt = 0; nt < 8; ++nt) {
            O[nt][0] *= al0; O[nt][1] *= al0; O[nt][2] *= al1; O[nt][3] *= al1;
        }

        // P -> bf16 hi/lo A-fragments, then O += P @ V
#pragma unroll
        for (int s = 0; s < 4; ++s) {
            unsigned ah[4], al[4];
#pragma unroll
            for (int half = 0; half < 2; ++half) {
                int t_ = 2 * s + half;
                float p0 = c[t_][0], p1 = c[t_][1], p2 = c[t_][2], p3 = c[t_][3];
                float h0 = __bfloat162float(__float2bfloat16_rn(p0));
                float h1 = __bfloat162float(__float2bfloat16_rn(p1));
                float h2 = __bfloat162float(__float2bfloat16_rn(p2));
                float h3 = __bfloat162float(__float2bfloat16_rn(p3));
                ah[2 * half] = packbf(h0, h1);
                ah[2 * half + 1] = packbf(h2, h3);
                al[2 * half] = packbf(p0 - h0, p1 - h1);
                al[2 * half + 1] = packbf(p2 - h2, p3 - h3);
            }
            // a-frag order: a0 r0 k0-7, a1 r1 k0-7, a2 r0 k8-15, a3 r1 k8-15
            unsigned AH[4] = {ah[0], ah[1], ah[2], ah[3]};
            unsigned AL[4] = {al[0], al[1], al[2], al[3]};
#pragma unroll
            for (int np = 0; np < 4; ++np) {
                unsigned bh_[4], bl_[4];
                ldmB2(bh_, Vh + np * 16 * VP + s * 16, VP);
                ldmB2(bl_, Vl + np * 16 * VP + s * 16, VP);
                mmabf(O[2 * np], AH, bh_[0], bh_[1]);
                mmabf(O[2 * np + 1], AH, bh_[2], bh_[3]);
                mmabf(O[2 * np], AH, bl_[0], bl_[1]);
                mmabf(O[2 * np + 1], AH, bl_[2], bl_[3]);
                mmabf(O[2 * np], AL, bh_[0], bh_[1]);
                mmabf(O[2 * np + 1], AL, bh_[2], bh_[3]);
            }
        }
    }

    float il0 = 1.0f / l0, il1 = 1.0f / l1;
    int r0 = q0 + wid * 16 + (lane >> 2);
    float* ob = o + ((long)b * SEQ + r0) * EDIM + h * DH;
#pragma unroll
    for (int nt = 0; nt < 8; ++nt) {
        int cc = nt * 8 + 2 * (lane & 3);
        *(float2*)(ob + cc) = make_float2(O[nt][0] * il0, O[nt][1] * il0);
        *(float2*)(ob + 8L * EDIM + cc) = make_float2(O[nt][2] * il1, O[nt][3] * il1);
    }
}

// ---------------- launch ----------------
extern "C" void kernel_launch(void* const* d_in, const int* in_sizes, int n_in,
                              void* d_out, int out_size) {
    const float* x  = (const float*)d_in[0];
    const float* Wq = (const float*)d_in[1];
    const float* bq = (const float*)d_in[2];
    const float* Wk = (const float*)d_in[3];
    const float* bk = (const float*)d_in[4];
    const float* Wv = (const float*)d_in[5];
    const float* bv = (const float*)d_in[6];
    const float* Wo = (const float*)d_in[7];
    const float* bo = (const float*)d_in[8];
    float* out = (float*)d_out;

    float *q, *k, *v, *ao, *st, *qn, *kn;
    __nv_bfloat16 *xcat, *wcat;
    cudaGetSymbolAddress((void**)&q, g_q);
    cudaGetSymbolAddress((void**)&k, g_k);
    cudaGetSymbolAddress((void**)&v, g_v);
    cudaGetSymbolAddress((void**)&ao, g_ao);
    cudaGetSymbolAddress((void**)&st, g_st);
    cudaGetSymbolAddress((void**)&qn, g_qn);
    cudaGetSymbolAddress((void**)&kn, g_kn);
    cudaGetSymbolAddress((void**)&xcat, g_xcat);
    cudaGetSymbolAddress((void**)&wcat, g_wcat);

    cudaFuncSetAttribute(attn_mma, cudaFuncAttributeMaxDynamicSharedMemorySize, ASMB);

    const long n2w = (long)EDIM * EDIM / 2;
    const long n2x = (long)ROWS * EDIM / 2;
    const long WSTR = (long)EDIM * KCAT;
    split_cat<<<(unsigned)((n2w + 255) / 256), 256>>>(Wq, wcat + 0 * WSTR, n2w, 1);
    split_cat<<<(unsigned)((n2w + 255) / 256), 256>>>(Wk, wcat + 1 * WSTR, n2w, 1);
    split_cat<<<(unsigned)((n2w + 255) / 256), 256>>>(Wv, wcat + 2 * WSTR, n2w, 1);
    split_cat<<<(unsigned)((n2w + 255) / 256), 256>>>(Wo, wcat + 3 * WSTR, n2w, 1);
    split_cat<<<(unsigned)((n2x + 255) / 256), 256>>>(x, xcat, n2x, 0);

    dim3 gg(EDIM / 128, ROWS / 128);   // (4, 64)
    gemm_bf16<<<gg, 256>>>(xcat, wcat + 0 * WSTR, q, ROWS, EDIM, KCAT);
    gemm_bf16<<<gg, 256>>>(xcat, wcat + 1 * WSTR, k, ROWS, EDIM, KCAT);
    gemm_bf16<<<gg, 256>>>(xcat, wcat + 2 * WSTR, v, ROWS, EDIM, KCAT);

    mobius_rows<<<ROWS, 128>>>(x, q, bq, q, qn, 1);
    mobius_rows<<<ROWS, 128>>>(x, k, bk, k, kn, 1);
    mobius_rows<<<ROWS, 128>>>(x, v, bv, v, nullptr, 0);

    dim3 ag(SEQ / 64, BH);             // (32, 32)
    attn_mma<<<ag, 128, ASMB>>>(q, k, v, qn, kn, ao);

    split_cat<<<(unsigned)((n2x + 255) / 256), 256>>>(ao, xcat, n2x, 0);
    gemm_bf16<<<gg, 256>>>(xcat, wcat + 3 * WSTR, st, ROWS, EDIM, KCAT);
    mobius_rows<<<ROWS, 128>>>(ao, st, bo, out, nullptr, 0);
}

// round 6
// speedup vs baseline: 3.0565x; 1.4711x over previous
#include <cuda_runtime.h>
#include <cuda_bf16.h>
#include <math.h>

#define EDIM 512
#define BDIM 4
#define SEQ  2048
#define NH   8
#define DH   64
#define ROWS (BDIM*SEQ)
#define BH   (BDIM*NH)
#define KCAT 1536
#define MAXNORM (1.0f - 4e-3f)

// ---------------- scratch ----------------
__device__ float g_q[ROWS*EDIM];
__device__ float g_k[ROWS*EDIM];
__device__ float g_v[ROWS*EDIM];
__device__ float g_ao[ROWS*EDIM];
__device__ float g_st[ROWS*EDIM];
__device__ __nv_bfloat16 g_xcat[(long)ROWS*KCAT];
__device__ __nv_bfloat16 g_wcat[4L*EDIM*KCAT];
__device__ __nv_bfloat16 g_qh[ROWS*EDIM];
__device__ __nv_bfloat16 g_kh[ROWS*EDIM];
__device__ __nv_bfloat16 g_vh[ROWS*EDIM];
__device__ __nv_bfloat16 g_vl[ROWS*EDIM];
__device__ float g_qn[BH*SEQ];
__device__ float g_kn[BH*SEQ];

// ---------------- mma helpers ----------------
__device__ __forceinline__ void ldmA(unsigned r[4], const __nv_bfloat16* p0, int pitch) {
    int l = threadIdx.x & 31;
    unsigned a = (unsigned)__cvta_generic_to_shared(p0 + (l & 15) * pitch + ((l >> 4) << 3));
    asm volatile("ldmatrix.sync.aligned.m8n8.x4.shared.b16 {%0,%1,%2,%3}, [%4];"
                 : "=r"(r[0]), "=r"(r[1]), "=r"(r[2]), "=r"(r[3]) : "r"(a));
}
// B-frags (2 n-tiles) from row-major [n][k] tile
__device__ __forceinline__ void ldmB2(unsigned r[4], const __nv_bfloat16* p0, int pitch) {
    int l = threadIdx.x & 31;
    unsigned a = (unsigned)__cvta_generic_to_shared(p0 + ((l & 7) + ((l >> 4) << 3)) * pitch + (l & 8));
    asm volatile("ldmatrix.sync.aligned.m8n8.x4.shared.b16 {%0,%1,%2,%3}, [%4];"
                 : "=r"(r[0]), "=r"(r[1]), "=r"(r[2]), "=r"(r[3]) : "r"(a));
}
// B-frags (2 n-tiles) from row-major [k][n] tile via trans (V natural layout)
__device__ __forceinline__ void ldmBt(unsigned r[4], const __nv_bfloat16* p0, int pitch) {
    int l = threadIdx.x & 31;
    unsigned a = (unsigned)__cvta_generic_to_shared(
        p0 + ((l & 7) + ((l >> 3) & 1) * 8) * pitch + ((l >> 4) << 3));
    asm volatile("ldmatrix.sync.aligned.m8n8.x4.trans.shared.b16 {%0,%1,%2,%3}, [%4];"
                 : "=r"(r[0]), "=r"(r[1]), "=r"(r[2]), "=r"(r[3]) : "r"(a));
}
__device__ __forceinline__ void mmabf(float c[4], const unsigned a[4], unsigned b0, unsigned b1) {
    asm volatile("mma.sync.aligned.m16n8k16.row.col.f32.bf16.bf16.f32 "
                 "{%0,%1,%2,%3},{%4,%5,%6,%7},{%8,%9},{%0,%1,%2,%3};"
                 : "+f"(c[0]), "+f"(c[1]), "+f"(c[2]), "+f"(c[3])
                 : "r"(a[0]), "r"(a[1]), "r"(a[2]), "r"(a[3]), "r"(b0), "r"(b1));
}
__device__ __forceinline__ unsigned packbf(float lo, float hi) {
    unsigned r;
    asm("cvt.rn.bf16x2.f32 %0, %1, %2;" : "=r"(r) : "f"(hi), "f"(lo));
    return r;
}

// ---------------- split_cat: fp32 -> bf16 [hi|hi|lo](pat0) / [hi|lo|hi](pat1) ----
__global__ __launch_bounds__(256) void split_cat(const float* __restrict__ src,
                                                 __nv_bfloat16* __restrict__ dst,
                                                 long n2, int pat) {
    long i = (long)blockIdx.x * blockDim.x + threadIdx.x;
    if (i >= n2) return;
    long e = i * 2;
    long r = e >> 9; int c = (int)(e & 511);
    float v0 = src[e], v1 = src[e + 1];
    __nv_bfloat16 h0 = __float2bfloat16_rn(v0), h1 = __float2bfloat16_rn(v1);
    __nv_bfloat16 l0 = __float2bfloat16_rn(v0 - __bfloat162float(h0));
    __nv_bfloat16 l1 = __float2bfloat16_rn(v1 - __bfloat162float(h1));
    __nv_bfloat16* p = dst + r * KCAT + c;
    p[0] = h0; p[1] = h1;
    if (pat == 0) { p[512] = h0; p[513] = h1; p[1024] = l0; p[1025] = l1; }
    else          { p[512] = l0; p[513] = l1; p[1024] = h0; p[1025] = h1; }
}

// ---------------- bf16 NT GEMM: C fp32 = A[M,K] @ B[N,K]^T, 128x128, BK=32 ----
__global__ __launch_bounds__(256) void gemm_bf16(const __nv_bfloat16* __restrict__ A,
                                                 const __nv_bfloat16* __restrict__ B,
                                                 float* __restrict__ C,
                                                 int M, int N, int K) {
    __shared__ __nv_bfloat16 As[128][40];
    __shared__ __nv_bfloat16 Bs[128][40];
    const int tid = threadIdx.x, lane = tid & 31, wid = tid >> 5;
    const int wm = wid & 3, wn = wid >> 2;
    const int bm = blockIdx.y * 128, bn = blockIdx.x * 128;

    float acc[2][8][4] = {};
    for (int kt = 0; kt < K; kt += 32) {
#pragma unroll
        for (int i = 0; i < 2; ++i) {
            int slot = tid + i * 256;
            int row = slot >> 2, ch = (slot & 3) * 8;
            *(uint4*)&As[row][ch] = *(const uint4*)&A[(long)(bm + row) * K + kt + ch];
            *(uint4*)&Bs[row][ch] = *(const uint4*)&B[(long)(bn + row) * K + kt + ch];
        }
        __syncthreads();
#pragma unroll
        for (int c = 0; c < 2; ++c) {
            unsigned a0[4], a1[4];
            ldmA(a0, &As[wm * 32][c * 16], 40);
            ldmA(a1, &As[wm * 32 + 16][c * 16], 40);
#pragma unroll
            for (int np = 0; np < 4; ++np) {
                unsigned b[4];
                ldmB2(b, &Bs[wn * 64 + np * 16][c * 16], 40);
                mmabf(acc[0][2 * np], a0, b[0], b[1]);
                mmabf(acc[0][2 * np + 1], a0, b[2], b[3]);
                mmabf(acc[1][2 * np], a1, b[0], b[1]);
                mmabf(acc[1][2 * np + 1], a1, b[2], b[3]);
            }
        }
        __syncthreads();
    }
#pragma unroll
    for (int mt = 0; mt < 2; ++mt) {
        int r0 = bm + wm * 32 + mt * 16 + (lane >> 2);
#pragma unroll
        for (int nt = 0; nt < 8; ++nt) {
            int cc = bn + wn * 64 + nt * 8 + 2 * (lane & 3);
            *(float2*)&C[(long)r0 * N + cc] = make_float2(acc[mt][nt][0], acc[mt][nt][1]);
            *(float2*)&C[(long)(r0 + 8) * N + cc] = make_float2(acc[mt][nt][2], acc[mt][nt][3]);
        }
    }
}

// ---------------- row-wise Mobius transform (+ optional bf16 hi/lo emit) ----
__device__ __forceinline__ float dot4(float4 a, float4 b) {
    return a.x * b.x + a.y * b.y + a.z * b.z + a.w * b.w;
}
__device__ __forceinline__ float warpSum(float v) {
#pragma unroll
    for (int o = 16; o > 0; o >>= 1) v += __shfl_xor_sync(0xffffffffu, v, o);
    return v;
}
__global__ __launch_bounds__(128) void mobius_rows(const float* __restrict__ x,
                                                   const float* __restrict__ mx,
                                                   const float* __restrict__ bias,
                                                   float* __restrict__ out,
                                                   float* __restrict__ hn,
                                                   __nv_bfloat16* __restrict__ ohi,
                                                   __nv_bfloat16* __restrict__ olo) {
    __shared__ float sa[4], sb[4], sc_[4];
    const int t = threadIdx.x, w = t >> 5, lane = t & 31;
    const long r = blockIdx.x;
    const float4 xv = ((const float4*)(x + r * EDIM))[t];
    const float4 mv = ((const float4*)(mx + r * EDIM))[t];
    const float4 bv = ((const float4*)bias)[t];

    float p1 = warpSum(dot4(xv, xv)), p2 = warpSum(dot4(mv, mv));
    if (lane == 0) { sa[w] = p1; sb[w] = p2; }
    __syncthreads();
    float x2 = sa[0] + sa[1] + sa[2] + sa[3];
    float m2 = sb[0] + sb[1] + sb[2] + sb[3];

    float xn = fmaxf(sqrtf(x2), 1e-15f);
    float mn = fmaxf(sqrtf(m2), 1e-15f);
    float u = fminf(xn, 1.0f - 1e-7f);
    float at = 0.5f * (log1pf(u) - log1pf(-u));
    float tt = tanhf(mn / xn * at);
    float sc = tt / mn;
    float4 res = make_float4(mv.x * sc, mv.y * sc, mv.z * sc, mv.w * sc);
    float rn = fmaxf(tt, 1e-15f);
    float pf = (rn > MAXNORM) ? (MAXNORM / rn) : 1.0f;
    res.x *= pf; res.y *= pf; res.z *= pf; res.w *= pf;

    __syncthreads();
    float q1 = warpSum(dot4(res, res)), q2 = warpSum(dot4(bv, bv)), q3 = warpSum(dot4(res, bv));
    if (lane == 0) { sa[w] = q1; sb[w] = q2; sc_[w] = q3; }
    __syncthreads();
    float x2r = sa[0] + sa[1] + sa[2] + sa[3];
    float y2 = sb[0] + sb[1] + sb[2] + sb[3];
    float xy = sc_[0] + sc_[1] + sc_[2] + sc_[3];
    float ca = 1.0f + 2.0f * xy + y2, cb = 1.0f - x2r;
    float den = fmaxf(1.0f + 2.0f * xy + x2r * y2, 1e-15f);
    float inv = 1.0f / den;
    float4 o = make_float4((ca * res.x + cb * bv.x) * inv, (ca * res.y + cb * bv.y) * inv,
                           (ca * res.z + cb * bv.z) * inv, (ca * res.w + cb * bv.w) * inv);
    __syncthreads();
    float q4 = warpSum(dot4(o, o));
    if (lane == 0) sa[w] = q4;
    __syncthreads();
    float o2 = sa[0] + sa[1] + sa[2] + sa[3];
    float on = fmaxf(sqrtf(o2), 1e-15f);
    float pf2 = (on > MAXNORM) ? (MAXNORM / on) : 1.0f;
    o.x *= pf2; o.y *= pf2; o.z *= pf2; o.w *= pf2;
    ((float4*)(out + r * EDIM))[t] = o;

    if (ohi) {
        float f[4] = {o.x, o.y, o.z, o.w};
        unsigned hpack[2];
        float hval[4];
#pragma unroll
        for (int j = 0; j < 2; ++j) {
            __nv_bfloat16 b0 = __float2bfloat16_rn(f[2 * j]);
            __nv_bfloat16 b1 = __float2bfloat16_rn(f[2 * j + 1]);
            hval[2 * j] = __bfloat162float(b0);
            hval[2 * j + 1] = __bfloat162float(b1);
            hpack[j] = ((unsigned)__bfloat16_as_ushort(b1) << 16) | __bfloat16_as_ushort(b0);
        }
        *(uint2*)(ohi + r * EDIM + t * 4) = make_uint2(hpack[0], hpack[1]);
        if (olo) {
            unsigned lp0 = packbf(f[0] - hval[0], f[1] - hval[1]);
            unsigned lp1 = packbf(f[2] - hval[2], f[3] - hval[3]);
            *(uint2*)(olo + r * EDIM + t * 4) = make_uint2(lp0, lp1);
        }
    }

    if (hn) {
        float h = dot4(o, o);
#pragma unroll
        for (int off = 8; off >= 1; off >>= 1) h += __shfl_xor_sync(0xffffffffu, h, off, 16);
        if ((t & 15) == 0) {
            int b = (int)(r / SEQ), s = (int)(r % SEQ);
            hn[((long)b * NH + (t >> 4)) * SEQ + s] = fminf(h, 1.0f - 1e-5f);
        }
    }
}

// ---------------- flash hyperbolic attention v2 ----------------
// 128 queries x 64-key tiles, 256 threads (8 warps x m16), bf16 tiles
// preconverted in gmem. QK single-pass bf16; PV 3-term hi/lo. Fixed softmax
// reference max m=0 (scores < 0 always).
#define AP 72
#define SCLAMP (-3.952847e-4f)   // -sqrt(1e-5)/8

__global__ __launch_bounds__(256) void attn2(const __nv_bfloat16* __restrict__ qh,
                                             const __nv_bfloat16* __restrict__ kh,
                                             const __nv_bfloat16* __restrict__ vh,
                                             const __nv_bfloat16* __restrict__ vl,
                                             const float* __restrict__ qn,
                                             const float* __restrict__ kn,
                                             float* __restrict__ o) {
    __shared__ __nv_bfloat16 Qs[128 * AP];
    __shared__ __nv_bfloat16 Ks[64 * AP];
    __shared__ __nv_bfloat16 Vhs[64 * AP];
    __shared__ __nv_bfloat16 Vls[64 * AP];
    __shared__ float qns[128], kns[64];

    const int tid = threadIdx.x, lane = tid & 31, w = tid >> 5;
    const int bh = blockIdx.y, b = bh >> 3, h = bh & 7;
    const int q0 = blockIdx.x * 128;
    const long qrow0 = (long)b * SEQ + q0;

#pragma unroll
    for (int it = 0; it < 4; ++it) {
        int slot = tid + it * 256;
        int r = slot >> 3, c8 = (slot & 7) * 8;
        *(uint4*)&Qs[r * AP + c8] = *(const uint4*)&qh[(qrow0 + r) * EDIM + h * DH + c8];
    }
    if (tid < 128) qns[tid] = qn[(long)bh * SEQ + q0 + tid];
    __syncthreads();

    const float qv0 = qns[w * 16 + (lane >> 2)];
    const float qv1 = qns[w * 16 + (lane >> 2) + 8];
    const float oq0 = 1.0f - qv0, oq1 = 1.0f - qv1;

    float O[8][4] = {};
    float ls0 = 0.0f, ls1 = 0.0f;

    for (int kt = 0; kt < SEQ; kt += 64) {
        __syncthreads();
        const long krow0 = (long)b * SEQ + kt;
#pragma unroll
        for (int it = 0; it < 2; ++it) {
            int slot = tid + it * 256;
            int r = slot >> 3, c8 = (slot & 7) * 8;
            long g = (krow0 + r) * EDIM + h * DH + c8;
            *(uint4*)&Ks[r * AP + c8]  = *(const uint4*)&kh[g];
            *(uint4*)&Vhs[r * AP + c8] = *(const uint4*)&vh[g];
            *(uint4*)&Vls[r * AP + c8] = *(const uint4*)&vl[g];
        }
        if (tid < 64) kns[tid] = kn[(long)bh * SEQ + kt + tid];
        __syncthreads();

        // S = Q K^T (bf16 single pass, K=64)
        float c[8][4] = {};
#pragma unroll
        for (int cs = 0; cs < 4; ++cs) {
            unsigned a[4];
            ldmA(a, Qs + (w * 16) * AP + cs * 16, AP);
#pragma unroll
            for (int np = 0; np < 4; ++np) {
                unsigned bb[4];
                ldmB2(bb, Ks + (np * 16) * AP + cs * 16, AP);
                mmabf(c[2 * np], a, bb[0], bb[1]);
                mmabf(c[2 * np + 1], a, bb[2], bb[3]);
            }
        }

        // hyperbolic score -> p = exp(score) (m = 0)
#pragma unroll
        for (int nt = 0; nt < 8; ++nt) {
#pragma unroll
            for (int e = 0; e < 4; ++e) {
                int col = nt * 8 + 2 * (lane & 3) + (e & 1);
                float kv = kns[col];
                float qq = (e < 2) ? qv0 : qv1;
                float oq = (e < 2) ? oq0 : oq1;
                float t2 = 2.0f * fmaf(-qq, kv, c[nt][e]);
                float dn = fmaf(oq, 1.0f - kv, 1e-5f);
                float s = t2 * __frsqrt_rn(t2 * dn) * (-0.125f);
                if (t2 <= 1e-5f * dn) s = SCLAMP;
                float p = __expf(s);
                c[nt][e] = p;
                if (e < 2) ls0 += p; else ls1 += p;
            }
        }

        // O += P V  (Ph*Vh + Ph*Vl + Pl*Vh)
#pragma unroll
        for (int s = 0; s < 4; ++s) {
            unsigned AH[4], AL[4];
#pragma unroll
            for (int half = 0; half < 2; ++half) {
                int t_ = 2 * s + half;
                float p0 = c[t_][0], p1 = c[t_][1], p2 = c[t_][2], p3 = c[t_][3];
                float h0 = __bfloat162float(__float2bfloat16_rn(p0));
                float h1 = __bfloat162float(__float2bfloat16_rn(p1));
                float h2 = __bfloat162float(__float2bfloat16_rn(p2));
                float h3 = __bfloat162float(__float2bfloat16_rn(p3));
                AH[2 * half]     = packbf(h0, h1);
                AH[2 * half + 1] = packbf(h2, h3);
                AL[2 * half]     = packbf(p0 - h0, p1 - h1);
                AL[2 * half + 1] = packbf(p2 - h2, p3 - h3);
            }
#pragma unroll
            for (int np = 0; np < 4; ++np) {
                unsigned bh_[4], bl_[4];
                ldmBt(bh_, Vhs + (s * 16) * AP + np * 16, AP);
                ldmBt(bl_, Vls + (s * 16) * AP + np * 16, AP);
                mmabf(O[2 * np],     AH, bh_[0], bh_[1]);
                mmabf(O[2 * np + 1], AH, bh_[2], bh_[3]);
                mmabf(O[2 * np],     AH, bl_[0], bl_[1]);
                mmabf(O[2 * np + 1], AH, bl_[2], bl_[3]);
                mmabf(O[2 * np],     AL, bh_[0], bh_[1]);
                mmabf(O[2 * np + 1], AL, bh_[2], bh_[3]);
            }
        }
    }

    ls0 += __shfl_xor_sync(0xffffffffu, ls0, 1);
    ls0 += __shfl_xor_sync(0xffffffffu, ls0, 2);
    ls1 += __shfl_xor_sync(0xffffffffu, ls1, 1);
    ls1 += __shfl_xor_sync(0xffffffffu, ls1, 2);
    float il0 = 1.0f / ls0, il1 = 1.0f / ls1;

    int r0 = q0 + w * 16 + (lane >> 2);
    float* ob = o + ((long)b * SEQ + r0) * EDIM + h * DH;
#pragma unroll
    for (int nt = 0; nt < 8; ++nt) {
        int cc = nt * 8 + 2 * (lane & 3);
        *(float2*)(ob + cc) = make_float2(O[nt][0] * il0, O[nt][1] * il0);
        *(float2*)(ob + 8L * EDIM + cc) = make_float2(O[nt][2] * il1, O[nt][3] * il1);
    }
}

// ---------------- launch ----------------
extern "C" void kernel_launch(void* const* d_in, const int* in_sizes, int n_in,
                              void* d_out, int out_size) {
    const float* x  = (const float*)d_in[0];
    const float* Wq = (const float*)d_in[1];
    const float* bq = (const float*)d_in[2];
    const float* Wk = (const float*)d_in[3];
    const float* bk = (const float*)d_in[4];
    const float* Wv = (const float*)d_in[5];
    const float* bv = (const float*)d_in[6];
    const float* Wo = (const float*)d_in[7];
    const float* bo = (const float*)d_in[8];
    float* out = (float*)d_out;

    float *q, *k, *v, *ao, *st, *qn, *kn;
    __nv_bfloat16 *xcat, *wcat, *qhb, *khb, *vhb, *vlb;
    cudaGetSymbolAddress((void**)&q, g_q);
    cudaGetSymbolAddress((void**)&k, g_k);
    cudaGetSymbolAddress((void**)&v, g_v);
    cudaGetSymbolAddress((void**)&ao, g_ao);
    cudaGetSymbolAddress((void**)&st, g_st);
    cudaGetSymbolAddress((void**)&qn, g_qn);
    cudaGetSymbolAddress((void**)&kn, g_kn);
    cudaGetSymbolAddress((void**)&xcat, g_xcat);
    cudaGetSymbolAddress((void**)&wcat, g_wcat);
    cudaGetSymbolAddress((void**)&qhb, g_qh);
    cudaGetSymbolAddress((void**)&khb, g_kh);
    cudaGetSymbolAddress((void**)&vhb, g_vh);
    cudaGetSymbolAddress((void**)&vlb, g_vl);

    const long n2w = (long)EDIM * EDIM / 2;
    const long n2x = (long)ROWS * EDIM / 2;
    const long WSTR = (long)EDIM * KCAT;
    split_cat<<<(unsigned)((n2w + 255) / 256), 256>>>(Wq, wcat + 0 * WSTR, n2w, 1);
    split_cat<<<(unsigned)((n2w + 255) / 256), 256>>>(Wk, wcat + 1 * WSTR, n2w, 1);
    split_cat<<<(unsigned)((n2w + 255) / 256), 256>>>(Wv, wcat + 2 * WSTR, n2w, 1);
    split_cat<<<(unsigned)((n2w + 255) / 256), 256>>>(Wo, wcat + 3 * WSTR, n2w, 1);
    split_cat<<<(unsigned)((n2x + 255) / 256), 256>>>(x, xcat, n2x, 0);

    dim3 gg(EDIM / 128, ROWS / 128);   // (4, 64)
    gemm_bf16<<<gg, 256>>>(xcat, wcat + 0 * WSTR, q, ROWS, EDIM, KCAT);
    gemm_bf16<<<gg, 256>>>(xcat, wcat + 1 * WSTR, k, ROWS, EDIM, KCAT);
    gemm_bf16<<<gg, 256>>>(xcat, wcat + 2 * WSTR, v, ROWS, EDIM, KCAT);

    mobius_rows<<<ROWS, 128>>>(x, q, bq, q, qn, qhb, nullptr);
    mobius_rows<<<ROWS, 128>>>(x, k, bk, k, kn, khb, nullptr);
    mobius_rows<<<ROWS, 128>>>(x, v, bv, v, nullptr, vhb, vlb);

    dim3 ag(SEQ / 128, BH);            // (16, 32)
    attn2<<<ag, 256>>>(qhb, khb, vhb, vlb, qn, kn, ao);

    split_cat<<<(unsigned)((n2x + 255) / 256), 256>>>(ao, xcat, n2x, 0);
    gemm_bf16<<<gg, 256>>>(xcat, wcat + 3 * WSTR, st, ROWS, EDIM, KCAT);
    mobius_rows<<<ROWS, 128>>>(ao, st, bo, out, nullptr, nullptr, nullptr);
}